// round 14
// baseline (speedup 1.0000x reference)
#include <cuda_runtime.h>
#include <cuda_bf16.h>
#include <math.h>

#define TOKENS 4096
#define DIM 1024
#define HALF 512
#define NUM_KEYS 512
#define TOPK 32
#define CHTOK 2048   // tokens per pipeline chunk

#define BM 128
#define BN 128
#define BK 8
#define MBK 16
#define PK  20
#define NSTAGE 3
#define MMA_SMEM (NSTAGE * (BM + BN) * PK * 4)

// ---------------- scratch (device globals; no allocation allowed) ----------------
__device__ float g_xh[TOKENS * DIM];       // tf32-rounded x
__device__ float g_wgh[DIM * DIM];         // tf32-rounded Wg
__device__ float g_woh[DIM * DIM];         // tf32-rounded Wo
__device__ float g_M[DIM * DIM];           // folded key matrix [1024 keys, 1024 d]
__device__ float g_c[DIM];                 // folded bias per key
__device__ float g_scores[TOKENS * DIM];   // [s1 | s2] per token
__device__ float g_gatepre[TOKENS * DIM];
__device__ float g_midh[TOKENS * DIM];
__device__ float g_w[TOKENS * TOPK];       // softmax weights
__device__ int   g_id[TOKENS * TOPK];      // selected value-row indices

// staircase candidate table: all (i,j) with (i+1)*(j+1) <= 32, packed (i<<8)|j.
__device__ const unsigned short g_ctbl[128] = {
    0x0000,0x0001,0x0002,0x0003,0x0004,0x0005,0x0006,0x0007,
    0x0008,0x0009,0x000A,0x000B,0x000C,0x000D,0x000E,0x000F,
    0x0010,0x0011,0x0012,0x0013,0x0014,0x0015,0x0016,0x0017,
    0x0018,0x0019,0x001A,0x001B,0x001C,0x001D,0x001E,0x001F,
    0x0100,0x0101,0x0102,0x0103,0x0104,0x0105,0x0106,0x0107,
    0x0108,0x0109,0x010A,0x010B,0x010C,0x010D,0x010E,0x010F,
    0x0200,0x0201,0x0202,0x0203,0x0204,0x0205,0x0206,0x0207,0x0208,0x0209,
    0x0300,0x0301,0x0302,0x0303,0x0304,0x0305,0x0306,0x0307,
    0x0400,0x0401,0x0402,0x0403,0x0404,0x0405,
    0x0500,0x0501,0x0502,0x0503,0x0504,
    0x0600,0x0601,0x0602,0x0603,
    0x0700,0x0701,0x0702,0x0703,
    0x0800,0x0801,0x0802,
    0x0900,0x0901,0x0902,
    0x0A00,0x0A01,0x0B00,0x0B01,0x0C00,0x0C01,
    0x0D00,0x0D01,0x0E00,0x0E01,0x0F00,0x0F01,
    0x1000,0x1100,0x1200,0x1300,0x1400,0x1500,0x1600,0x1700,
    0x1800,0x1900,0x1A00,0x1B00,0x1C00,0x1D00,0x1E00,0x1F00,
    0xFFFF,0xFFFF,0xFFFF,0xFFFF,0xFFFF,0xFFFF,0xFFFF,0xFFFF,0xFFFF
};

// ---------------- helpers --------------------------------------------------------
__device__ __forceinline__ unsigned f2tf(float x) {
    unsigned r;
    asm("cvt.rna.tf32.f32 %0, %1;" : "=r"(r) : "f"(x));
    return r;
}
__device__ __forceinline__ float tf32f(float x) { return __uint_as_float(f2tf(x)); }

__device__ __forceinline__ void mma8(float* c, const unsigned* a, const unsigned* b) {
    asm volatile("mma.sync.aligned.m16n8k8.row.col.f32.tf32.tf32.f32 "
                 "{%0,%1,%2,%3}, {%4,%5,%6,%7}, {%8,%9}, {%0,%1,%2,%3};"
                 : "+f"(c[0]), "+f"(c[1]), "+f"(c[2]), "+f"(c[3])
                 : "r"(a[0]), "r"(a[1]), "r"(a[2]), "r"(a[3]),
                   "r"(b[0]), "r"(b[1]));
}
__device__ __forceinline__ void cp16(unsigned sdst, const void* gsrc) {
    asm volatile("cp.async.cg.shared.global [%0], [%1], 16;" :: "r"(sdst), "l"(gsrc));
}

// ================= fp32 SIMT TN GEMM, BK=8 (exact path: scores) ==================
__global__ __launch_bounds__(256, 2)
void gemm_tn2(const float* __restrict__ A, int lda,
              const float* __restrict__ B, int ldb,
              float* __restrict__ C, int ldc,
              const float* __restrict__ bias,
              int K)
{
    __shared__ __align__(16) float As[2][BK][BM];
    __shared__ __align__(16) float Bs[2][BK][BN];

    const int tid = threadIdx.x;
    const int m0 = blockIdx.y * BM;
    const int n0 = blockIdx.x * BN;

    const int lrow = tid >> 1;
    const int lk4  = (tid & 1) * 4;
    const float* Aload = A + (size_t)(m0 + lrow) * lda + lk4;
    const float* Bload = B + (size_t)(n0 + lrow) * ldb + lk4;

    const int tx = tid & 15;
    const int ty = tid >> 4;

    float acc[8][8];
#pragma unroll
    for (int i = 0; i < 8; i++)
#pragma unroll
        for (int j = 0; j < 8; j++) acc[i][j] = 0.f;

    float4 av = *reinterpret_cast<const float4*>(Aload);
    float4 bv = *reinterpret_cast<const float4*>(Bload);
    As[0][lk4 + 0][lrow] = av.x;
    As[0][lk4 + 1][lrow] = av.y;
    As[0][lk4 + 2][lrow] = av.z;
    As[0][lk4 + 3][lrow] = av.w;
    Bs[0][lk4 + 0][lrow] = bv.x;
    Bs[0][lk4 + 1][lrow] = bv.y;
    Bs[0][lk4 + 2][lrow] = bv.z;
    Bs[0][lk4 + 3][lrow] = bv.w;
    __syncthreads();

    const int nstages = K / BK;
    int buf = 0;
    for (int s = 0; s < nstages; ++s) {
        if (s + 1 < nstages) {
            av = *reinterpret_cast<const float4*>(Aload + (size_t)(s + 1) * BK);
            bv = *reinterpret_cast<const float4*>(Bload + (size_t)(s + 1) * BK);
        }
#pragma unroll
        for (int k = 0; k < BK; k++) {
            float4 a0 = *reinterpret_cast<const float4*>(&As[buf][k][ty * 4]);
            float4 a1 = *reinterpret_cast<const float4*>(&As[buf][k][64 + ty * 4]);
            float4 b0 = *reinterpret_cast<const float4*>(&Bs[buf][k][tx * 4]);
            float4 b1 = *reinterpret_cast<const float4*>(&Bs[buf][k][64 + tx * 4]);
            float ar[8] = {a0.x, a0.y, a0.z, a0.w, a1.x, a1.y, a1.z, a1.w};
            float br[8] = {b0.x, b0.y, b0.z, b0.w, b1.x, b1.y, b1.z, b1.w};
#pragma unroll
            for (int i = 0; i < 8; i++)
#pragma unroll
                for (int j = 0; j < 8; j++)
                    acc[i][j] = fmaf(ar[i], br[j], acc[i][j]);
        }
        if (s + 1 < nstages) {
            int nb = buf ^ 1;
            As[nb][lk4 + 0][lrow] = av.x;
            As[nb][lk4 + 1][lrow] = av.y;
            As[nb][lk4 + 2][lrow] = av.z;
            As[nb][lk4 + 3][lrow] = av.w;
            Bs[nb][lk4 + 0][lrow] = bv.x;
            Bs[nb][lk4 + 1][lrow] = bv.y;
            Bs[nb][lk4 + 2][lrow] = bv.z;
            Bs[nb][lk4 + 3][lrow] = bv.w;
        }
        __syncthreads();
        buf ^= 1;
    }

    const int nc0 = n0 + tx * 4;
    const int nc1 = n0 + 64 + tx * 4;
    float4 bb0 = *reinterpret_cast<const float4*>(&bias[nc0]);
    float4 bb1 = *reinterpret_cast<const float4*>(&bias[nc1]);
#pragma unroll
    for (int i = 0; i < 8; i++) {
        int m = m0 + ((i < 4) ? (ty * 4 + i) : (64 + ty * 4 + i - 4));
        float* Crow = C + (size_t)m * ldc;
        float4 o0 = make_float4(acc[i][0] + bb0.x, acc[i][1] + bb0.y,
                                acc[i][2] + bb0.z, acc[i][3] + bb0.w);
        float4 o1 = make_float4(acc[i][4] + bb1.x, acc[i][5] + bb1.y,
                                acc[i][6] + bb1.z, acc[i][7] + bb1.w);
        *reinterpret_cast<float4*>(&Crow[nc0]) = o0;
        *reinterpret_cast<float4*>(&Crow[nc1]) = o1;
    }
}

// ================= tf32 tensor-core TN GEMM, 3-stage pipeline ====================
__global__ __launch_bounds__(256, 2)
void gemm_mma_tf32(const float* __restrict__ A, int lda,
                   const float* __restrict__ B, int ldb,
                   float* __restrict__ C, int ldc,
                   const float* __restrict__ bias, int K)
{
    extern __shared__ __align__(16) float smem_dyn[];
    typedef float TileT[BM][PK];
    TileT* As = reinterpret_cast<TileT*>(smem_dyn);
    TileT* Bs = reinterpret_cast<TileT*>(smem_dyn + NSTAGE * BM * PK);

    const int tid  = threadIdx.x;
    const int lane = tid & 31, warp = tid >> 5;
    const int gid  = lane >> 2, tig = lane & 3;
    const int wm = (warp & 1) * 64;
    const int wn = (warp >> 1) * 32;
    const int m0 = blockIdx.y * BM, n0 = blockIdx.x * BN;

    const int srow = tid >> 1;
    const int scol = (tid & 1) * 8;

    float acc[4][4][4];
#pragma unroll
    for (int mi = 0; mi < 4; mi++)
#pragma unroll
        for (int ni = 0; ni < 4; ni++)
#pragma unroll
            for (int r = 0; r < 4; r++) acc[mi][ni][r] = 0.f;

    auto ldst = [&](int s) {
        int buf = s % NSTAGE;
        const float* ag = A + (size_t)(m0 + srow) * lda + s * MBK + scol;
        const float* bg = B + (size_t)(n0 + srow) * ldb + s * MBK + scol;
        unsigned sa = (unsigned)__cvta_generic_to_shared(&As[buf][srow][scol]);
        unsigned sb = (unsigned)__cvta_generic_to_shared(&Bs[buf][srow][scol]);
        cp16(sa, ag); cp16(sa + 16, ag + 4);
        cp16(sb, bg); cp16(sb + 16, bg + 4);
    };

    const int nst = K / MBK;
    ldst(0);
    asm volatile("cp.async.commit_group;");
    if (nst > 1) ldst(1);
    asm volatile("cp.async.commit_group;");

    for (int s = 0; s < nst; ++s) {
        if (s == nst - 1) {
            asm volatile("cp.async.wait_group 0;");
        } else {
            asm volatile("cp.async.wait_group 1;");
        }
        __syncthreads();
        if (s + 2 < nst) {
            ldst(s + 2);
            asm volatile("cp.async.commit_group;");
        } else {
            asm volatile("cp.async.commit_group;");
        }

        const int buf = s % NSTAGE;
#pragma unroll
        for (int kk = 0; kk < 2; ++kk) {
            const int k0 = kk * 8;
            unsigned a[4][4], b[4][2];
#pragma unroll
            for (int mi = 0; mi < 4; ++mi) {
                int r0 = wm + mi * 16 + gid;
                a[mi][0] = *(const unsigned*)&As[buf][r0][k0 + tig];
                a[mi][1] = *(const unsigned*)&As[buf][r0 + 8][k0 + tig];
                a[mi][2] = *(const unsigned*)&As[buf][r0][k0 + tig + 4];
                a[mi][3] = *(const unsigned*)&As[buf][r0 + 8][k0 + tig + 4];
            }
#pragma unroll
            for (int ni = 0; ni < 4; ++ni) {
                int r = wn + ni * 8 + gid;
                b[ni][0] = *(const unsigned*)&Bs[buf][r][k0 + tig];
                b[ni][1] = *(const unsigned*)&Bs[buf][r][k0 + tig + 4];
            }
#pragma unroll
            for (int mi = 0; mi < 4; ++mi)
#pragma unroll
                for (int ni = 0; ni < 4; ++ni)
                    mma8(acc[mi][ni], a[mi], b[ni]);
        }
    }

#pragma unroll
    for (int ni = 0; ni < 4; ++ni) {
        int c0 = n0 + wn + ni * 8 + tig * 2;
        float2 bb = *reinterpret_cast<const float2*>(&bias[c0]);
#pragma unroll
        for (int mi = 0; mi < 4; ++mi) {
            int r = m0 + wm + mi * 16 + gid;
            *reinterpret_cast<float2*>(&C[(size_t)r * ldc + c0]) =
                make_float2(acc[mi][ni][0] + bb.x, acc[mi][ni][1] + bb.y);
            *reinterpret_cast<float2*>(&C[(size_t)(r + 8) * ldc + c0]) =
                make_float2(acc[mi][ni][2] + bb.x, acc[mi][ni][3] + bb.y);
        }
    }
}

// ================= branch A kernel: mprep + cfold ================================
__global__ __launch_bounds__(256)
void prep_mp(const float* __restrict__ Wq, const float* __restrict__ bq,
             const float* __restrict__ ke1, const float* __restrict__ ke2,
             float* __restrict__ M, float* __restrict__ c)
{
    __shared__ __align__(16) float As[16][64];
    __shared__ __align__(16) float Bs[16][64];
    const int bid = blockIdx.x;
    const int tid = threadIdx.x;

    if (bid < 256) {
        const int m0 = (bid >> 4) * 64;
        const int n0 = (bid & 15) * 64;
        const float* Arow = (m0 < NUM_KEYS) ? (ke1 + (size_t)m0 * HALF)
                                            : (ke2 + (size_t)(m0 - NUM_KEYS) * HALF);
        const int woff = (m0 < NUM_KEYS) ? 0 : HALF;

        const int lr  = tid >> 2;
        const int lc4 = (tid & 3) * 4;
        const int bk  = tid >> 4;
        const int bn4 = (tid & 15) * 4;
        const int tx = tid & 15;
        const int ty = tid >> 4;

        float acc[4][4];
#pragma unroll
        for (int i = 0; i < 4; i++)
#pragma unroll
            for (int j = 0; j < 4; j++) acc[i][j] = 0.f;

        for (int k0 = 0; k0 < HALF; k0 += 16) {
            float4 av = *reinterpret_cast<const float4*>(&Arow[(size_t)lr * HALF + k0 + lc4]);
            As[lc4 + 0][lr] = av.x;
            As[lc4 + 1][lr] = av.y;
            As[lc4 + 2][lr] = av.z;
            As[lc4 + 3][lr] = av.w;
            float4 bv = *reinterpret_cast<const float4*>(&Wq[(size_t)(woff + k0 + bk) * DIM + n0 + bn4]);
            *reinterpret_cast<float4*>(&Bs[bk][bn4]) = bv;
            __syncthreads();
#pragma unroll
            for (int k = 0; k < 16; k++) {
                float4 a = reinterpret_cast<float4*>(As[k])[ty];
                float4 b = reinterpret_cast<float4*>(Bs[k])[tx];
                float ar[4] = {a.x, a.y, a.z, a.w};
                float br[4] = {b.x, b.y, b.z, b.w};
#pragma unroll
                for (int i = 0; i < 4; i++)
#pragma unroll
                    for (int j = 0; j < 4; j++)
                        acc[i][j] = fmaf(ar[i], br[j], acc[i][j]);
            }
            __syncthreads();
        }
#pragma unroll
        for (int i = 0; i < 4; i++) {
            int m = m0 + ty * 4 + i;
            float4 o = make_float4(acc[i][0], acc[i][1], acc[i][2], acc[i][3]);
            *reinterpret_cast<float4*>(&M[(size_t)m * DIM + n0 + tx * 4]) = o;
        }
    } else {
        int w = (bid - 256) * 8 + (tid >> 5);
        int lane = tid & 31;
        const float* ke = (w < NUM_KEYS) ? (ke1 + (size_t)w * HALF)
                                         : (ke2 + (size_t)(w - NUM_KEYS) * HALF);
        const float* b  = (w < NUM_KEYS) ? bq : bq + HALF;
        float s = 0.f;
#pragma unroll
        for (int j = 0; j < 16; ++j)
            s = fmaf(ke[lane + j * 32], b[lane + j * 32], s);
#pragma unroll
        for (int sh = 16; sh > 0; sh >>= 1) s += __shfl_xor_sync(0xffffffffu, s, sh);
        if (lane == 0) c[w] = s;
    }
}

// ================= branch B kernel: tf32-round x, Wg, Wo =========================
#define P4_X ((TOKENS * DIM) / 4)
#define P4_W ((DIM * DIM) / 4)
#define P4_TOT (P4_X + 2 * P4_W)
#define PREP_BLOCKS ((P4_TOT + 255) / 256)

__global__ __launch_bounds__(256)
void prep_round(const float* __restrict__ x, const float* __restrict__ Wg,
                const float* __restrict__ Wo,
                float* __restrict__ xh, float* __restrict__ wgh, float* __restrict__ woh)
{
    int i = blockIdx.x * 256 + threadIdx.x;
    if (i >= P4_TOT) return;
    const float4* src; float4* dst; int off;
    if (i < P4_X)             { src = (const float4*)x;  dst = (float4*)xh;  off = i; }
    else if (i < P4_X + P4_W) { src = (const float4*)Wg; dst = (float4*)wgh; off = i - P4_X; }
    else                      { src = (const float4*)Wo; dst = (float4*)woh; off = i - P4_X - P4_W; }
    float4 v = src[off];
    dst[off] = make_float4(tf32f(v.x), tf32f(v.y), tf32f(v.z), tf32f(v.w));
}

// ================= topk + combine + softmax (8 tokens/block) =====================
__device__ __forceinline__ void warp_topk512(const float* __restrict__ src, int lane,
                                             float* __restrict__ outv, int* __restrict__ outi)
{
    float v[16];
#pragma unroll
    for (int j = 0; j < 16; j++) v[j] = src[j * 32 + lane];

    float lm = v[0]; int lj = 0;
#pragma unroll
    for (int j = 1; j < 16; j++)
        if (v[j] > lm) { lm = v[j]; lj = j; }

    for (int it = 0; it < TOPK; ++it) {
        float bv = lm;
        int bi = lj * 32 + lane;
#pragma unroll
        for (int s = 16; s > 0; s >>= 1) {
            float ov = __shfl_xor_sync(0xffffffffu, bv, s);
            int   oi = __shfl_xor_sync(0xffffffffu, bi, s);
            if (ov > bv || (ov == bv && oi < bi)) { bv = ov; bi = oi; }
        }
        if (lane == 0) { outv[it] = bv; outi[it] = bi; }
        if ((bi & 31) == lane) {
            int jd = bi >> 5;
#pragma unroll
            for (int j = 0; j < 16; j++)
                if (j == jd) v[j] = -INFINITY;
            lm = -INFINITY; lj = 0;
#pragma unroll
            for (int j = 0; j < 16; j++)
                if (v[j] > lm) { lm = v[j]; lj = j; }
        }
    }
}

__global__ __launch_bounds__(256)
void topk_combine(const float* __restrict__ scores,
                  float* __restrict__ gw, int* __restrict__ gid)
{
    const int base = blockIdx.x * 8;          // 8 tokens per block
    const int tid = threadIdx.x;
    const int lane = tid & 31;
    const int wid = tid >> 5;                 // 0..7

    __shared__ float sv[8][2][TOPK];
    __shared__ int   si[8][2][TOPK];
    __shared__ float cw[8][TOPK];

#pragma unroll
    for (int pass = 0; pass < 2; ++pass) {
        int T = wid + pass * 8;
        int tl = T >> 1, which = T & 1;
        const float* src = scores + (size_t)(base + tl) * DIM + which * HALF;
        warp_topk512(src, lane, sv[tl][which], si[tl][which]);
    }
    __syncthreads();

    {
        const int tl = wid;
        const int token = base + tl;
        const float* s1v = sv[tl][0];
        const float* s2v = sv[tl][1];
        const int*   s1i = si[tl][0];
        const int*   s2i = si[tl][1];

        float cv[4]; int cp[4];
#pragma unroll
        for (int q = 0; q < 4; ++q) {
            unsigned e = g_ctbl[lane + q * 32];
            if (e != 0xFFFFu) {
                int ci = e >> 8, cj = e & 0xFF;
                cv[q] = s1v[ci] + s2v[cj];
                cp[q] = ci * 32 + cj;
            } else {
                cv[q] = -INFINITY;
                cp[q] = 0x7FFFFFFF;
            }
        }
        float lm = cv[0]; int lp = cp[0]; int lq = 0;
#pragma unroll
        for (int q = 1; q < 4; ++q)
            if (cv[q] > lm || (cv[q] == lm && cp[q] < lp)) { lm = cv[q]; lp = cp[q]; lq = q; }

        for (int it = 0; it < TOPK; ++it) {
            float bv = lm; int bp = lp;
#pragma unroll
            for (int s = 16; s > 0; s >>= 1) {
                float ov = __shfl_xor_sync(0xffffffffu, bv, s);
                int   op = __shfl_xor_sync(0xffffffffu, bp, s);
                if (ov > bv || (ov == bv && op < bp)) { bv = ov; bp = op; }
            }
            if (lane == 0) {
                cw[tl][it] = bv;
                gid[(size_t)token * TOPK + it] = s1i[bp >> 5] * NUM_KEYS + s2i[bp & 31];
            }
            if (lp == bp) {
#pragma unroll
                for (int q = 0; q < 4; ++q)
                    if (q == lq) { cv[q] = -INFINITY; cp[q] = 0x7FFFFFFF; }
                lm = cv[0]; lp = cp[0]; lq = 0;
#pragma unroll
                for (int q = 1; q < 4; ++q)
                    if (cv[q] > lm || (cv[q] == lm && cp[q] < lp)) { lm = cv[q]; lp = cp[q]; lq = q; }
            }
            __syncwarp();
        }
        float v = cw[tl][lane] * (1.0f / 32.0f);
        float mx = v;
#pragma unroll
        for (int s = 16; s > 0; s >>= 1) mx = fmaxf(mx, __shfl_xor_sync(0xffffffffu, mx, s));
        float e = expf(v - mx);
        float sum = e;
#pragma unroll
        for (int s = 16; s > 0; s >>= 1) sum += __shfl_xor_sync(0xffffffffu, sum, s);
        gw[(size_t)token * TOPK + lane] = e / sum;
    }
}

// ================= gather + silu gate (pure DRAM-bound) ==========================
__global__ __launch_bounds__(256)
void gather_kernel(const float* __restrict__ gw, const int* __restrict__ gid,
                   const float* __restrict__ values,
                   const float* __restrict__ gatepre,
                   float* __restrict__ midh)
{
    const int token = blockIdx.x;
    const int tid = threadIdx.x;

    __shared__ float w[TOPK];
    __shared__ int   id[TOPK];
    if (tid < TOPK) {
        w[tid]  = gw[(size_t)token * TOPK + tid];
        id[tid] = gid[(size_t)token * TOPK + tid];
    }
    __syncthreads();

    float4 acc = make_float4(0.f, 0.f, 0.f, 0.f);
#pragma unroll 8
    for (int k = 0; k < TOPK; ++k) {
        float wk = w[k];
        const float4* row = reinterpret_cast<const float4*>(values + (size_t)id[k] * DIM);
        float4 r = __ldg(&row[tid]);
        acc.x = fmaf(wk, r.x, acc.x);
        acc.y = fmaf(wk, r.y, acc.y);
        acc.z = fmaf(wk, r.z, acc.z);
        acc.w = fmaf(wk, r.w, acc.w);
    }
    float4 gp = reinterpret_cast<const float4*>(gatepre + (size_t)token * DIM)[tid];
    float4 o;
    o.x = tf32f(acc.x * (gp.x / (1.f + expf(-gp.x))));
    o.y = tf32f(acc.y * (gp.y / (1.f + expf(-gp.y))));
    o.z = tf32f(acc.z * (gp.z / (1.f + expf(-gp.z))));
    o.w = tf32f(acc.w * (gp.w / (1.f + expf(-gp.w))));
    reinterpret_cast<float4*>(midh + (size_t)token * DIM)[tid] = o;
}

// ---------------- launch ---------------------------------------------------------
extern "C" void kernel_launch(void* const* d_in, const int* in_sizes, int n_in,
                              void* d_out, int out_size)
{
    const float* x      = (const float*)d_in[0];
    const float* ke1    = (const float*)d_in[1];
    const float* ke2    = (const float*)d_in[2];
    const float* values = (const float*)d_in[3];
    const float* Wq     = (const float*)d_in[4];
    const float* bq     = (const float*)d_in[5];
    const float* Wg     = (const float*)d_in[6];
    const float* bg     = (const float*)d_in[7];
    const float* Wo     = (const float*)d_in[8];
    const float* bo     = (const float*)d_in[9];
    float* out = (float*)d_out;

    float *xh, *wgh, *woh, *M, *c, *scores, *gatepre, *midh, *gw;
    int *gid;
    cudaGetSymbolAddress((void**)&xh,  g_xh);
    cudaGetSymbolAddress((void**)&wgh, g_wgh);
    cudaGetSymbolAddress((void**)&woh, g_woh);
    cudaGetSymbolAddress((void**)&M,   g_M);
    cudaGetSymbolAddress((void**)&c,   g_c);
    cudaGetSymbolAddress((void**)&scores,  g_scores);
    cudaGetSymbolAddress((void**)&gatepre, g_gatepre);
    cudaGetSymbolAddress((void**)&midh,    g_midh);
    cudaGetSymbolAddress((void**)&gw,  g_w);
    cudaGetSymbolAddress((void**)&gid, g_id);

    cudaFuncSetAttribute(gemm_mma_tf32, cudaFuncAttributeMaxDynamicSharedMemorySize,
                         MMA_SMEM);

    // streams + events (host-side objects, created once; no device allocation)
    static cudaStream_t sB = nullptr, sC = nullptr;
    static cudaEvent_t evFork = nullptr, evG = nullptr, evS[2] = {nullptr, nullptr};
    static cudaEvent_t evB = nullptr;
    if (sB == nullptr) {
        cudaStreamCreateWithFlags(&sB, cudaStreamNonBlocking);
        cudaStreamCreateWithFlags(&sC, cudaStreamNonBlocking);
        cudaEventCreateWithFlags(&evFork, cudaEventDisableTiming);
        cudaEventCreateWithFlags(&evG, cudaEventDisableTiming);
        cudaEventCreateWithFlags(&evS[0], cudaEventDisableTiming);
        cudaEventCreateWithFlags(&evS[1], cudaEventDisableTiming);
        cudaEventCreateWithFlags(&evB, cudaEventDisableTiming);
    }

    dim3 blk(256);

    // fork
    cudaEventRecord(evFork, 0);
    cudaStreamWaitEvent(sC, evFork, 0);
    cudaStreamWaitEvent(sB, evFork, 0);

    // stream C: tf32 rounding -> gatepre mma
    prep_round<<<PREP_BLOCKS, blk, 0, sC>>>(x, Wg, Wo, xh, wgh, woh);
    gemm_mma_tf32<<<dim3(DIM / BN, TOKENS / BM), blk, MMA_SMEM, sC>>>(
        xh, DIM, wgh, DIM, gatepre, DIM, bg, DIM);
    cudaEventRecord(evG, sC);

    // main stream: mprep+cfold, then scores per chunk
    prep_mp<<<384, blk>>>(Wq, bq, ke1, ke2, M, c);
    for (int ch = 0; ch < 2; ++ch) {
        const float* xA   = x + (size_t)ch * CHTOK * DIM;
        float* scC        = scores + (size_t)ch * CHTOK * DIM;
        gemm_tn2<<<dim3(DIM / BN, CHTOK / BM), blk>>>(xA, DIM, M, DIM, scC, DIM, c, DIM);
        cudaEventRecord(evS[ch], 0);
    }

    // stream B: per-chunk topk -> gather -> out
    cudaStreamWaitEvent(sB, evG, 0);
    for (int ch = 0; ch < 2; ++ch) {
        size_t toff = (size_t)ch * CHTOK;
        cudaStreamWaitEvent(sB, evS[ch], 0);
        topk_combine<<<CHTOK / 8, blk, 0, sB>>>(
            scores + toff * DIM, gw + toff * TOPK, gid + toff * TOPK);
        gather_kernel<<<CHTOK, blk, 0, sB>>>(
            gw + toff * TOPK, gid + toff * TOPK, values,
            gatepre + toff * DIM, midh + toff * DIM);
        gemm_mma_tf32<<<dim3(DIM / BN, CHTOK / BM), blk, MMA_SMEM, sB>>>(
            midh + toff * DIM, DIM, woh, DIM, out + toff * DIM, DIM, bo, DIM);
    }
    cudaEventRecord(evB, sB);

    // join everything back to the origin stream
    cudaStreamWaitEvent(0, evB, 0);
}

// round 15
// speedup vs baseline: 1.1847x; 1.1847x over previous
#include <cuda_runtime.h>
#include <cuda_bf16.h>
#include <math.h>

#define TOKENS 4096
#define DIM 1024
#define HALF 512
#define NUM_KEYS 512
#define TOPK 32

#define BM 128
#define BN 128
#define BK 8
#define MBK 16
#define PK  20
#define NSTAGE 3
#define MMA_SMEM (NSTAGE * (BM + BN) * PK * 4)

// ---------------- scratch (device globals; no allocation allowed) ----------------
__device__ float g_xh[TOKENS * DIM];       // tf32-rounded x
__device__ float g_wgh[DIM * DIM];         // tf32-rounded Wg
__device__ float g_woh[DIM * DIM];         // tf32-rounded Wo
__device__ float g_M[DIM * DIM];           // folded key matrix [1024 keys, 1024 d]
__device__ float g_c[DIM];                 // folded bias per key
__device__ float g_scores[TOKENS * DIM];   // [s1 | s2] per token
__device__ float g_gatepre[TOKENS * DIM];
__device__ float g_midh[TOKENS * DIM];
__device__ float g_w[TOKENS * TOPK];       // softmax weights
__device__ int   g_id[TOKENS * TOPK];      // selected value-row indices

// staircase candidate table: all (i,j) with (i+1)*(j+1) <= 32, packed (i<<8)|j.
__device__ const unsigned short g_ctbl[128] = {
    0x0000,0x0001,0x0002,0x0003,0x0004,0x0005,0x0006,0x0007,
    0x0008,0x0009,0x000A,0x000B,0x000C,0x000D,0x000E,0x000F,
    0x0010,0x0011,0x0012,0x0013,0x0014,0x0015,0x0016,0x0017,
    0x0018,0x0019,0x001A,0x001B,0x001C,0x001D,0x001E,0x001F,
    0x0100,0x0101,0x0102,0x0103,0x0104,0x0105,0x0106,0x0107,
    0x0108,0x0109,0x010A,0x010B,0x010C,0x010D,0x010E,0x010F,
    0x0200,0x0201,0x0202,0x0203,0x0204,0x0205,0x0206,0x0207,0x0208,0x0209,
    0x0300,0x0301,0x0302,0x0303,0x0304,0x0305,0x0306,0x0307,
    0x0400,0x0401,0x0402,0x0403,0x0404,0x0405,
    0x0500,0x0501,0x0502,0x0503,0x0504,
    0x0600,0x0601,0x0602,0x0603,
    0x0700,0x0701,0x0702,0x0703,
    0x0800,0x0801,0x0802,
    0x0900,0x0901,0x0902,
    0x0A00,0x0A01,0x0B00,0x0B01,0x0C00,0x0C01,
    0x0D00,0x0D01,0x0E00,0x0E01,0x0F00,0x0F01,
    0x1000,0x1100,0x1200,0x1300,0x1400,0x1500,0x1600,0x1700,
    0x1800,0x1900,0x1A00,0x1B00,0x1C00,0x1D00,0x1E00,0x1F00,
    0xFFFF,0xFFFF,0xFFFF,0xFFFF,0xFFFF,0xFFFF,0xFFFF,0xFFFF,0xFFFF
};

// ---------------- helpers --------------------------------------------------------
__device__ __forceinline__ unsigned f2tf(float x) {
    unsigned r;
    asm("cvt.rna.tf32.f32 %0, %1;" : "=r"(r) : "f"(x));
    return r;
}
__device__ __forceinline__ float tf32f(float x) { return __uint_as_float(f2tf(x)); }

__device__ __forceinline__ void mma8(float* c, const unsigned* a, const unsigned* b) {
    asm volatile("mma.sync.aligned.m16n8k8.row.col.f32.tf32.tf32.f32 "
                 "{%0,%1,%2,%3}, {%4,%5,%6,%7}, {%8,%9}, {%0,%1,%2,%3};"
                 : "+f"(c[0]), "+f"(c[1]), "+f"(c[2]), "+f"(c[3])
                 : "r"(a[0]), "r"(a[1]), "r"(a[2]), "r"(a[3]),
                   "r"(b[0]), "r"(b[1]));
}
__device__ __forceinline__ void cp16(unsigned sdst, const void* gsrc) {
    asm volatile("cp.async.cg.shared.global [%0], [%1], 16;" :: "r"(sdst), "l"(gsrc));
}

// packed f32x2 helpers (Blackwell): lane-wise fp32 ops on a 64-bit pair.
// lo lane = first operand of mov.b64 {lo, hi}.
__device__ __forceinline__ unsigned long long pk2(float lo, float hi) {
    unsigned long long r;
    asm("mov.b64 %0, {%1, %2};" : "=l"(r) : "f"(lo), "f"(hi));
    return r;
}
__device__ __forceinline__ void upk2(unsigned long long v, float& lo, float& hi) {
    asm("mov.b64 {%0, %1}, %2;" : "=f"(lo), "=f"(hi) : "l"(v));
}
__device__ __forceinline__ void fma2(unsigned long long& c,
                                     unsigned long long a, unsigned long long b) {
    asm("fma.rn.f32x2 %0, %1, %2, %0;" : "+l"(c) : "l"(a), "l"(b));
}

// ================= fp32 SIMT TN GEMM, BK=8, FFMA2 inner loop =====================
// Accumulators packed along the row dim: acc2[ip][j] holds rows (2ip,2ip+1), col j.
// Each scalar lane performs the SAME fmaf in the SAME k order as the scalar
// version -> bit-identical scores.
__global__ __launch_bounds__(256, 2)
void gemm_tn2(const float* __restrict__ A, int lda,
              const float* __restrict__ B, int ldb,
              float* __restrict__ C, int ldc,
              const float* __restrict__ bias,
              int K)
{
    __shared__ __align__(16) float As[2][BK][BM];
    __shared__ __align__(16) float Bs[2][BK][BN];

    const int tid = threadIdx.x;
    const int m0 = blockIdx.y * BM;
    const int n0 = blockIdx.x * BN;

    const int lrow = tid >> 1;
    const int lk4  = (tid & 1) * 4;
    const float* Aload = A + (size_t)(m0 + lrow) * lda + lk4;
    const float* Bload = B + (size_t)(n0 + lrow) * ldb + lk4;

    const int tx = tid & 15;
    const int ty = tid >> 4;

    unsigned long long acc2[4][8];
#pragma unroll
    for (int ip = 0; ip < 4; ip++)
#pragma unroll
        for (int j = 0; j < 8; j++) acc2[ip][j] = 0ull;

    float4 av = *reinterpret_cast<const float4*>(Aload);
    float4 bv = *reinterpret_cast<const float4*>(Bload);
    As[0][lk4 + 0][lrow] = av.x;
    As[0][lk4 + 1][lrow] = av.y;
    As[0][lk4 + 2][lrow] = av.z;
    As[0][lk4 + 3][lrow] = av.w;
    Bs[0][lk4 + 0][lrow] = bv.x;
    Bs[0][lk4 + 1][lrow] = bv.y;
    Bs[0][lk4 + 2][lrow] = bv.z;
    Bs[0][lk4 + 3][lrow] = bv.w;
    __syncthreads();

    const int nstages = K / BK;
    int buf = 0;
    for (int s = 0; s < nstages; ++s) {
        if (s + 1 < nstages) {
            av = *reinterpret_cast<const float4*>(Aload + (size_t)(s + 1) * BK);
            bv = *reinterpret_cast<const float4*>(Bload + (size_t)(s + 1) * BK);
        }
#pragma unroll
        for (int k = 0; k < BK; k++) {
            float4 a0 = *reinterpret_cast<const float4*>(&As[buf][k][ty * 4]);
            float4 a1 = *reinterpret_cast<const float4*>(&As[buf][k][64 + ty * 4]);
            float4 b0 = *reinterpret_cast<const float4*>(&Bs[buf][k][tx * 4]);
            float4 b1 = *reinterpret_cast<const float4*>(&Bs[buf][k][64 + tx * 4]);
            // row pairs (free views of float4 halves)
            unsigned long long ap[4];
            ap[0] = pk2(a0.x, a0.y);
            ap[1] = pk2(a0.z, a0.w);
            ap[2] = pk2(a1.x, a1.y);
            ap[3] = pk2(a1.z, a1.w);
            // column broadcasts
            unsigned long long bd[8];
            bd[0] = pk2(b0.x, b0.x);
            bd[1] = pk2(b0.y, b0.y);
            bd[2] = pk2(b0.z, b0.z);
            bd[3] = pk2(b0.w, b0.w);
            bd[4] = pk2(b1.x, b1.x);
            bd[5] = pk2(b1.y, b1.y);
            bd[6] = pk2(b1.z, b1.z);
            bd[7] = pk2(b1.w, b1.w);
#pragma unroll
            for (int ip = 0; ip < 4; ip++)
#pragma unroll
                for (int j = 0; j < 8; j++)
                    fma2(acc2[ip][j], ap[ip], bd[j]);
        }
        if (s + 1 < nstages) {
            int nb = buf ^ 1;
            As[nb][lk4 + 0][lrow] = av.x;
            As[nb][lk4 + 1][lrow] = av.y;
            As[nb][lk4 + 2][lrow] = av.z;
            As[nb][lk4 + 3][lrow] = av.w;
            Bs[nb][lk4 + 0][lrow] = bv.x;
            Bs[nb][lk4 + 1][lrow] = bv.y;
            Bs[nb][lk4 + 2][lrow] = bv.z;
            Bs[nb][lk4 + 3][lrow] = bv.w;
        }
        __syncthreads();
        buf ^= 1;
    }

    const int nc0 = n0 + tx * 4;
    const int nc1 = n0 + 64 + tx * 4;
    float4 bb0 = *reinterpret_cast<const float4*>(&bias[nc0]);
    float4 bb1 = *reinterpret_cast<const float4*>(&bias[nc1]);
#pragma unroll
    for (int i = 0; i < 8; i++) {
        int m = m0 + ((i < 4) ? (ty * 4 + i) : (64 + ty * 4 + i - 4));
        float* Crow = C + (size_t)m * ldc;
        const int ip = i >> 1;
        float r[8];
#pragma unroll
        for (int j = 0; j < 8; j++) {
            float lo, hi;
            upk2(acc2[ip][j], lo, hi);
            r[j] = (i & 1) ? hi : lo;
        }
        float4 o0 = make_float4(r[0] + bb0.x, r[1] + bb0.y, r[2] + bb0.z, r[3] + bb0.w);
        float4 o1 = make_float4(r[4] + bb1.x, r[5] + bb1.y, r[6] + bb1.z, r[7] + bb1.w);
        *reinterpret_cast<float4*>(&Crow[nc0]) = o0;
        *reinterpret_cast<float4*>(&Crow[nc1]) = o1;
    }
}

// ================= tf32 tensor-core TN GEMM, 3-stage pipeline ====================
__global__ __launch_bounds__(256, 2)
void gemm_mma_tf32(const float* __restrict__ A, int lda,
                   const float* __restrict__ B, int ldb,
                   float* __restrict__ C, int ldc,
                   const float* __restrict__ bias, int K)
{
    extern __shared__ __align__(16) float smem_dyn[];
    typedef float TileT[BM][PK];
    TileT* As = reinterpret_cast<TileT*>(smem_dyn);
    TileT* Bs = reinterpret_cast<TileT*>(smem_dyn + NSTAGE * BM * PK);

    const int tid  = threadIdx.x;
    const int lane = tid & 31, warp = tid >> 5;
    const int gid  = lane >> 2, tig = lane & 3;
    const int wm = (warp & 1) * 64;
    const int wn = (warp >> 1) * 32;
    const int m0 = blockIdx.y * BM, n0 = blockIdx.x * BN;

    const int srow = tid >> 1;
    const int scol = (tid & 1) * 8;

    float acc[4][4][4];
#pragma unroll
    for (int mi = 0; mi < 4; mi++)
#pragma unroll
        for (int ni = 0; ni < 4; ni++)
#pragma unroll
            for (int r = 0; r < 4; r++) acc[mi][ni][r] = 0.f;

    auto ldst = [&](int s) {
        int buf = s % NSTAGE;
        const float* ag = A + (size_t)(m0 + srow) * lda + s * MBK + scol;
        const float* bg = B + (size_t)(n0 + srow) * ldb + s * MBK + scol;
        unsigned sa = (unsigned)__cvta_generic_to_shared(&As[buf][srow][scol]);
        unsigned sb = (unsigned)__cvta_generic_to_shared(&Bs[buf][srow][scol]);
        cp16(sa, ag); cp16(sa + 16, ag + 4);
        cp16(sb, bg); cp16(sb + 16, bg + 4);
    };

    const int nst = K / MBK;
    ldst(0);
    asm volatile("cp.async.commit_group;");
    if (nst > 1) ldst(1);
    asm volatile("cp.async.commit_group;");

    for (int s = 0; s < nst; ++s) {
        if (s == nst - 1) {
            asm volatile("cp.async.wait_group 0;");
        } else {
            asm volatile("cp.async.wait_group 1;");
        }
        __syncthreads();
        if (s + 2 < nst) {
            ldst(s + 2);
            asm volatile("cp.async.commit_group;");
        } else {
            asm volatile("cp.async.commit_group;");
        }

        const int buf = s % NSTAGE;
#pragma unroll
        for (int kk = 0; kk < 2; ++kk) {
            const int k0 = kk * 8;
            unsigned a[4][4], b[4][2];
#pragma unroll
            for (int mi = 0; mi < 4; ++mi) {
                int r0 = wm + mi * 16 + gid;
                a[mi][0] = *(const unsigned*)&As[buf][r0][k0 + tig];
                a[mi][1] = *(const unsigned*)&As[buf][r0 + 8][k0 + tig];
                a[mi][2] = *(const unsigned*)&As[buf][r0][k0 + tig + 4];
                a[mi][3] = *(const unsigned*)&As[buf][r0 + 8][k0 + tig + 4];
            }
#pragma unroll
            for (int ni = 0; ni < 4; ++ni) {
                int r = wn + ni * 8 + gid;
                b[ni][0] = *(const unsigned*)&Bs[buf][r][k0 + tig];
                b[ni][1] = *(const unsigned*)&Bs[buf][r][k0 + tig + 4];
            }
#pragma unroll
            for (int mi = 0; mi < 4; ++mi)
#pragma unroll
                for (int ni = 0; ni < 4; ++ni)
                    mma8(acc[mi][ni], a[mi], b[ni]);
        }
    }

#pragma unroll
    for (int ni = 0; ni < 4; ++ni) {
        int c0 = n0 + wn + ni * 8 + tig * 2;
        float2 bb = *reinterpret_cast<const float2*>(&bias[c0]);
#pragma unroll
        for (int mi = 0; mi < 4; ++mi) {
            int r = m0 + wm + mi * 16 + gid;
            *reinterpret_cast<float2*>(&C[(size_t)r * ldc + c0]) =
                make_float2(acc[mi][ni][0] + bb.x, acc[mi][ni][1] + bb.y);
            *reinterpret_cast<float2*>(&C[(size_t)(r + 8) * ldc + c0]) =
                make_float2(acc[mi][ni][2] + bb.x, acc[mi][ni][3] + bb.y);
        }
    }
}

// ================= branch A kernel: mprep + cfold ================================
__global__ __launch_bounds__(256)
void prep_mp(const float* __restrict__ Wq, const float* __restrict__ bq,
             const float* __restrict__ ke1, const float* __restrict__ ke2,
             float* __restrict__ M, float* __restrict__ c)
{
    __shared__ __align__(16) float As[16][64];
    __shared__ __align__(16) float Bs[16][64];
    const int bid = blockIdx.x;
    const int tid = threadIdx.x;

    if (bid < 256) {
        const int m0 = (bid >> 4) * 64;
        const int n0 = (bid & 15) * 64;
        const float* Arow = (m0 < NUM_KEYS) ? (ke1 + (size_t)m0 * HALF)
                                            : (ke2 + (size_t)(m0 - NUM_KEYS) * HALF);
        const int woff = (m0 < NUM_KEYS) ? 0 : HALF;

        const int lr  = tid >> 2;
        const int lc4 = (tid & 3) * 4;
        const int bk  = tid >> 4;
        const int bn4 = (tid & 15) * 4;
        const int tx = tid & 15;
        const int ty = tid >> 4;

        float acc[4][4];
#pragma unroll
        for (int i = 0; i < 4; i++)
#pragma unroll
            for (int j = 0; j < 4; j++) acc[i][j] = 0.f;

        for (int k0 = 0; k0 < HALF; k0 += 16) {
            float4 av = *reinterpret_cast<const float4*>(&Arow[(size_t)lr * HALF + k0 + lc4]);
            As[lc4 + 0][lr] = av.x;
            As[lc4 + 1][lr] = av.y;
            As[lc4 + 2][lr] = av.z;
            As[lc4 + 3][lr] = av.w;
            float4 bv = *reinterpret_cast<const float4*>(&Wq[(size_t)(woff + k0 + bk) * DIM + n0 + bn4]);
            *reinterpret_cast<float4*>(&Bs[bk][bn4]) = bv;
            __syncthreads();
#pragma unroll
            for (int k = 0; k < 16; k++) {
                float4 a = reinterpret_cast<float4*>(As[k])[ty];
                float4 b = reinterpret_cast<float4*>(Bs[k])[tx];
                float ar[4] = {a.x, a.y, a.z, a.w};
                float br[4] = {b.x, b.y, b.z, b.w};
#pragma unroll
                for (int i = 0; i < 4; i++)
#pragma unroll
                    for (int j = 0; j < 4; j++)
                        acc[i][j] = fmaf(ar[i], br[j], acc[i][j]);
            }
            __syncthreads();
        }
#pragma unroll
        for (int i = 0; i < 4; i++) {
            int m = m0 + ty * 4 + i;
            float4 o = make_float4(acc[i][0], acc[i][1], acc[i][2], acc[i][3]);
            *reinterpret_cast<float4*>(&M[(size_t)m * DIM + n0 + tx * 4]) = o;
        }
    } else {
        int w = (bid - 256) * 8 + (tid >> 5);
        int lane = tid & 31;
        const float* ke = (w < NUM_KEYS) ? (ke1 + (size_t)w * HALF)
                                         : (ke2 + (size_t)(w - NUM_KEYS) * HALF);
        const float* b  = (w < NUM_KEYS) ? bq : bq + HALF;
        float s = 0.f;
#pragma unroll
        for (int j = 0; j < 16; ++j)
            s = fmaf(ke[lane + j * 32], b[lane + j * 32], s);
#pragma unroll
        for (int sh = 16; sh > 0; sh >>= 1) s += __shfl_xor_sync(0xffffffffu, s, sh);
        if (lane == 0) c[w] = s;
    }
}

// ================= branch B kernel: tf32-round x, Wg, Wo =========================
#define P4_X ((TOKENS * DIM) / 4)
#define P4_W ((DIM * DIM) / 4)
#define P4_TOT (P4_X + 2 * P4_W)
#define PREP_BLOCKS ((P4_TOT + 255) / 256)

__global__ __launch_bounds__(256)
void prep_round(const float* __restrict__ x, const float* __restrict__ Wg,
                const float* __restrict__ Wo,
                float* __restrict__ xh, float* __restrict__ wgh, float* __restrict__ woh)
{
    int i = blockIdx.x * 256 + threadIdx.x;
    if (i >= P4_TOT) return;
    const float4* src; float4* dst; int off;
    if (i < P4_X)             { src = (const float4*)x;  dst = (float4*)xh;  off = i; }
    else if (i < P4_X + P4_W) { src = (const float4*)Wg; dst = (float4*)wgh; off = i - P4_X; }
    else                      { src = (const float4*)Wo; dst = (float4*)woh; off = i - P4_X - P4_W; }
    float4 v = src[off];
    dst[off] = make_float4(tf32f(v.x), tf32f(v.y), tf32f(v.z), tf32f(v.w));
}

// ================= topk + combine + softmax (8 tokens/block) =====================
__device__ __forceinline__ void warp_topk512(const float* __restrict__ src, int lane,
                                             float* __restrict__ outv, int* __restrict__ outi)
{
    float v[16];
#pragma unroll
    for (int j = 0; j < 16; j++) v[j] = src[j * 32 + lane];

    float lm = v[0]; int lj = 0;
#pragma unroll
    for (int j = 1; j < 16; j++)
        if (v[j] > lm) { lm = v[j]; lj = j; }

    for (int it = 0; it < TOPK; ++it) {
        float bv = lm;
        int bi = lj * 32 + lane;
#pragma unroll
        for (int s = 16; s > 0; s >>= 1) {
            float ov = __shfl_xor_sync(0xffffffffu, bv, s);
            int   oi = __shfl_xor_sync(0xffffffffu, bi, s);
            if (ov > bv || (ov == bv && oi < bi)) { bv = ov; bi = oi; }
        }
        if (lane == 0) { outv[it] = bv; outi[it] = bi; }
        if ((bi & 31) == lane) {
            int jd = bi >> 5;
#pragma unroll
            for (int j = 0; j < 16; j++)
                if (j == jd) v[j] = -INFINITY;
            lm = -INFINITY; lj = 0;
#pragma unroll
            for (int j = 0; j < 16; j++)
                if (v[j] > lm) { lm = v[j]; lj = j; }
        }
    }
}

__global__ __launch_bounds__(256)
void topk_combine(const float* __restrict__ scores,
                  float* __restrict__ gw, int* __restrict__ gid)
{
    const int base = blockIdx.x * 8;          // 8 tokens per block
    const int tid = threadIdx.x;
    const int lane = tid & 31;
    const int wid = tid >> 5;                 // 0..7

    __shared__ float sv[8][2][TOPK];
    __shared__ int   si[8][2][TOPK];
    __shared__ float cw[8][TOPK];

#pragma unroll
    for (int pass = 0; pass < 2; ++pass) {
        int T = wid + pass * 8;
        int tl = T >> 1, which = T & 1;
        const float* src = scores + (size_t)(base + tl) * DIM + which * HALF;
        warp_topk512(src, lane, sv[tl][which], si[tl][which]);
    }
    __syncthreads();

    {
        const int tl = wid;
        const int token = base + tl;
        const float* s1v = sv[tl][0];
        const float* s2v = sv[tl][1];
        const int*   s1i = si[tl][0];
        const int*   s2i = si[tl][1];

        float cv[4]; int cp[4];
#pragma unroll
        for (int q = 0; q < 4; ++q) {
            unsigned e = g_ctbl[lane + q * 32];
            if (e != 0xFFFFu) {
                int ci = e >> 8, cj = e & 0xFF;
                cv[q] = s1v[ci] + s2v[cj];
                cp[q] = ci * 32 + cj;
            } else {
                cv[q] = -INFINITY;
                cp[q] = 0x7FFFFFFF;
            }
        }
        float lm = cv[0]; int lp = cp[0]; int lq = 0;
#pragma unroll
        for (int q = 1; q < 4; ++q)
            if (cv[q] > lm || (cv[q] == lm && cp[q] < lp)) { lm = cv[q]; lp = cp[q]; lq = q; }

        for (int it = 0; it < TOPK; ++it) {
            float bv = lm; int bp = lp;
#pragma unroll
            for (int s = 16; s > 0; s >>= 1) {
                float ov = __shfl_xor_sync(0xffffffffu, bv, s);
                int   op = __shfl_xor_sync(0xffffffffu, bp, s);
                if (ov > bv || (ov == bv && op < bp)) { bv = ov; bp = op; }
            }
            if (lane == 0) {
                cw[tl][it] = bv;
                gid[(size_t)token * TOPK + it] = s1i[bp >> 5] * NUM_KEYS + s2i[bp & 31];
            }
            if (lp == bp) {
#pragma unroll
                for (int q = 0; q < 4; ++q)
                    if (q == lq) { cv[q] = -INFINITY; cp[q] = 0x7FFFFFFF; }
                lm = cv[0]; lp = cp[0]; lq = 0;
#pragma unroll
                for (int q = 1; q < 4; ++q)
                    if (cv[q] > lm || (cv[q] == lm && cp[q] < lp)) { lm = cv[q]; lp = cp[q]; lq = q; }
            }
            __syncwarp();
        }
        float v = cw[tl][lane] * (1.0f / 32.0f);
        float mx = v;
#pragma unroll
        for (int s = 16; s > 0; s >>= 1) mx = fmaxf(mx, __shfl_xor_sync(0xffffffffu, mx, s));
        float e = expf(v - mx);
        float sum = e;
#pragma unroll
        for (int s = 16; s > 0; s >>= 1) sum += __shfl_xor_sync(0xffffffffu, sum, s);
        gw[(size_t)token * TOPK + lane] = e / sum;
    }
}

// ================= gather + silu gate (pure DRAM-bound) ==========================
__global__ __launch_bounds__(256)
void gather_kernel(const float* __restrict__ gw, const int* __restrict__ gid,
                   const float* __restrict__ values,
                   const float* __restrict__ gatepre,
                   float* __restrict__ midh)
{
    const int token = blockIdx.x;
    const int tid = threadIdx.x;

    __shared__ float w[TOPK];
    __shared__ int   id[TOPK];
    if (tid < TOPK) {
        w[tid]  = gw[(size_t)token * TOPK + tid];
        id[tid] = gid[(size_t)token * TOPK + tid];
    }
    __syncthreads();

    float4 acc = make_float4(0.f, 0.f, 0.f, 0.f);
#pragma unroll 8
    for (int k = 0; k < TOPK; ++k) {
        float wk = w[k];
        const float4* row = reinterpret_cast<const float4*>(values + (size_t)id[k] * DIM);
        float4 r = __ldg(&row[tid]);
        acc.x = fmaf(wk, r.x, acc.x);
        acc.y = fmaf(wk, r.y, acc.y);
        acc.z = fmaf(wk, r.z, acc.z);
        acc.w = fmaf(wk, r.w, acc.w);
    }
    float4 gp = reinterpret_cast<const float4*>(gatepre + (size_t)token * DIM)[tid];
    float4 o;
    o.x = tf32f(acc.x * (gp.x / (1.f + expf(-gp.x))));
    o.y = tf32f(acc.y * (gp.y / (1.f + expf(-gp.y))));
    o.z = tf32f(acc.z * (gp.z / (1.f + expf(-gp.z))));
    o.w = tf32f(acc.w * (gp.w / (1.f + expf(-gp.w))));
    reinterpret_cast<float4*>(midh + (size_t)token * DIM)[tid] = o;
}

// ---------------- launch ---------------------------------------------------------
extern "C" void kernel_launch(void* const* d_in, const int* in_sizes, int n_in,
                              void* d_out, int out_size)
{
    const float* x      = (const float*)d_in[0];
    const float* ke1    = (const float*)d_in[1];
    const float* ke2    = (const float*)d_in[2];
    const float* values = (const float*)d_in[3];
    const float* Wq     = (const float*)d_in[4];
    const float* bq     = (const float*)d_in[5];
    const float* Wg     = (const float*)d_in[6];
    const float* bg     = (const float*)d_in[7];
    const float* Wo     = (const float*)d_in[8];
    const float* bo     = (const float*)d_in[9];
    float* out = (float*)d_out;

    float *xh, *wgh, *woh, *M, *c, *scores, *gatepre, *midh, *gw;
    int *gid;
    cudaGetSymbolAddress((void**)&xh,  g_xh);
    cudaGetSymbolAddress((void**)&wgh, g_wgh);
    cudaGetSymbolAddress((void**)&woh, g_woh);
    cudaGetSymbolAddress((void**)&M,   g_M);
    cudaGetSymbolAddress((void**)&c,   g_c);
    cudaGetSymbolAddress((void**)&scores,  g_scores);
    cudaGetSymbolAddress((void**)&gatepre, g_gatepre);
    cudaGetSymbolAddress((void**)&midh,    g_midh);
    cudaGetSymbolAddress((void**)&gw,  g_w);
    cudaGetSymbolAddress((void**)&gid, g_id);

    cudaFuncSetAttribute(gemm_mma_tf32, cudaFuncAttributeMaxDynamicSharedMemorySize,
                         MMA_SMEM);

    // side stream + fork/join events (host-side objects, created once)
    static cudaStream_t s2 = nullptr;
    static cudaEvent_t evFork = nullptr, evJoin = nullptr;
    if (s2 == nullptr) {
        cudaStreamCreateWithFlags(&s2, cudaStreamNonBlocking);
        cudaEventCreateWithFlags(&evFork, cudaEventDisableTiming);
        cudaEventCreateWithFlags(&evJoin, cudaEventDisableTiming);
    }

    dim3 blk(256);

    // fork: branch B (s2) = tf32 rounding -> gatepre mma
    cudaEventRecord(evFork, 0);
    cudaStreamWaitEvent(s2, evFork, 0);

    prep_round<<<PREP_BLOCKS, blk, 0, s2>>>(x, Wg, Wo, xh, wgh, woh);
    gemm_mma_tf32<<<dim3(DIM / BN, TOKENS / BM), blk, MMA_SMEM, s2>>>(
        xh, DIM, wgh, DIM, gatepre, DIM, bg, DIM);
    cudaEventRecord(evJoin, s2);

    // branch A (main stream): mprep+cfold -> scores (FFMA2) -> topk
    prep_mp<<<384, blk>>>(Wq, bq, ke1, ke2, M, c);
    gemm_tn2<<<dim3(DIM / BN, TOKENS / BM), blk>>>(x, DIM, M, DIM, scores, DIM, c, DIM);
    topk_combine<<<TOKENS / 8, blk>>>(scores, gw, gid);

    // join: gather needs gatepre (branch B) + topk outputs (branch A)
    cudaStreamWaitEvent(0, evJoin, 0);
    gather_kernel<<<TOKENS, blk>>>(gw, gid, values, gatepre, midh);

    // out = mid @ Wo^T + bo (tf32 mma, 3-stage pipeline)
    gemm_mma_tf32<<<dim3(DIM / BN, TOKENS / BM), blk, MMA_SMEM>>>(
        midh, DIM, woh, DIM, out, DIM, bo, DIM);
}